// round 15
// baseline (speedup 1.0000x reference)
#include <cuda_runtime.h>
#include <cuda_bf16.h>
#include <cstdint>

#define M_DIM 8192
#define K_DIM 4096
#define N_DIM 11008

// ---------- device scratch (no allocs allowed) ----------
__device__ __align__(256) __nv_bfloat16 g_A[(size_t)M_DIM * K_DIM];
__device__ __align__(256) __nv_bfloat16 g_W[(size_t)N_DIM * K_DIM];
__device__ float g_scale_col[N_DIM];
__device__ float g_x_scale[M_DIM];
__device__ int   g_mask[K_DIM];
__device__ int   g_tile_ctr;

// ---------- helpers ----------
__device__ __forceinline__ uint32_t smem_u32(const void* p) {
    uint32_t a;
    asm("{ .reg .u64 t; cvta.to.shared.u64 t, %1; cvt.u32.u64 %0, t; }" : "=r"(a) : "l"(p));
    return a;
}
#define SWZ(o) ((o) ^ (((o) >> 3) & 0x70))

__device__ __forceinline__ float block_max_256(float v) {
    __shared__ float red[8];
    #pragma unroll
    for (int o = 16; o > 0; o >>= 1) v = fmaxf(v, __shfl_xor_sync(0xffffffffu, v, o));
    if ((threadIdx.x & 31) == 0) red[threadIdx.x >> 5] = v;
    __syncthreads();
    if (threadIdx.x < 32) {
        float t = (threadIdx.x < 8) ? red[threadIdx.x] : 0.0f;
        #pragma unroll
        for (int o = 4; o > 0; o >>= 1) t = fmaxf(t, __shfl_xor_sync(0xffffffffu, t, o));
        if (threadIdx.x == 0) red[0] = t;
    }
    __syncthreads();
    return red[0];
}

// ---------- preprocessing ----------
constexpr int NCTA = 148;

__global__ void clear_mask_kernel() {
    int i = blockIdx.x * blockDim.x + threadIdx.x;
    if (i < K_DIM) g_mask[i] = 0;
    if (i == 0) g_tile_ctr = NCTA;   // tiles 0..NCTA-1 statically seeded
}

// fused: blocks [0, N_DIM) do weight quant; blocks [N_DIM, ...) do the outlier mask.
__global__ void wq_mask_kernel(const float* __restrict__ w, const float* __restrict__ x,
                               const float* __restrict__ sigma) {
    if (blockIdx.x < N_DIM) {
        int n = blockIdx.x;
        const float4* row = reinterpret_cast<const float4*>(w + (size_t)n * K_DIM);
        float4 v[4];
        float mx = 0.0f;
        #pragma unroll
        for (int i = 0; i < 4; i++) {
            v[i] = row[threadIdx.x + i * 256];
            mx = fmaxf(mx, fmaxf(fmaxf(fabsf(v[i].x), fabsf(v[i].y)),
                                 fmaxf(fabsf(v[i].z), fabsf(v[i].w))));
        }
        mx = block_max_256(mx);
        float scale = mx * (1.0f / 64.0f);
        if (threadIdx.x == 0) g_scale_col[n] = scale;
        float inv = 1.0f / scale;
        ushort4* dst = reinterpret_cast<ushort4*>(g_W + (size_t)n * K_DIM);
        #pragma unroll
        for (int i = 0; i < 4; i++) {
            ushort4 u;
            u.x = __bfloat16_as_ushort(__float2bfloat16_rn(rintf(v[i].x * inv)));
            u.y = __bfloat16_as_ushort(__float2bfloat16_rn(rintf(v[i].y * inv)));
            u.z = __bfloat16_as_ushort(__float2bfloat16_rn(rintf(v[i].z * inv)));
            u.w = __bfloat16_as_ushort(__float2bfloat16_rn(rintf(v[i].w * inv)));
            dst[threadIdx.x + i * 256] = u;
        }
    } else {
        float sig = *sigma;
        size_t i = (size_t)(blockIdx.x - N_DIM) * blockDim.x + threadIdx.x;
        float4 v = reinterpret_cast<const float4*>(x)[i];
        int base = (int)((i * 4) & (K_DIM - 1));
        if (fabsf(v.x) > sig) g_mask[base + 0] = 1;
        if (fabsf(v.y) > sig) g_mask[base + 1] = 1;
        if (fabsf(v.z) > sig) g_mask[base + 2] = 1;
        if (fabsf(v.w) > sig) g_mask[base + 3] = 1;
    }
}

__global__ void rowquant_kernel(const float* __restrict__ x) {
    int m = blockIdx.x;
    const float4* row = reinterpret_cast<const float4*>(x + (size_t)m * K_DIM);
    const int4* mrow = reinterpret_cast<const int4*>(g_mask);
    float4 v[4];
    int4 mk[4];
    float mx = 0.0f;
    #pragma unroll
    for (int i = 0; i < 4; i++) {
        int f = threadIdx.x + i * 256;
        v[i] = row[f];
        mk[i] = mrow[f];
        if (!mk[i].x) mx = fmaxf(mx, fabsf(v[i].x));
        if (!mk[i].y) mx = fmaxf(mx, fabsf(v[i].y));
        if (!mk[i].z) mx = fmaxf(mx, fabsf(v[i].z));
        if (!mk[i].w) mx = fmaxf(mx, fabsf(v[i].w));
    }
    mx = block_max_256(mx);
    float xs = fmaxf(mx * (1.0f / 127.0f), 1e-8f);
    if (threadIdx.x == 0) g_x_scale[m] = xs;
    float inv = 1.0f / xs;
    ushort4* dst = reinterpret_cast<ushort4*>(g_A + (size_t)m * K_DIM);
    #pragma unroll
    for (int i = 0; i < 4; i++) {
        int f = threadIdx.x + i * 256;
        float q0 = v[i].x * inv; if (!mk[i].x) q0 = rintf(q0);
        float q1 = v[i].y * inv; if (!mk[i].y) q1 = rintf(q1);
        float q2 = v[i].z * inv; if (!mk[i].z) q2 = rintf(q2);
        float q3 = v[i].w * inv; if (!mk[i].w) q3 = rintf(q3);
        ushort4 u;
        u.x = __bfloat16_as_ushort(__float2bfloat16_rn(q0));
        u.y = __bfloat16_as_ushort(__float2bfloat16_rn(q1));
        u.z = __bfloat16_as_ushort(__float2bfloat16_rn(q2));
        u.w = __bfloat16_as_ushort(__float2bfloat16_rn(q3));
        dst[f] = u;
    }
}

// ---------- persistent GEMM: mma.sync bf16, 128x256x64 tile, 4 stages, work-stealing ----------
constexpr int BM = 128, BN = 256, BK = 64;
constexpr int STAGES = 4;
constexpr int KSTEPS = K_DIM / BK;                  // 64 (multiple of STAGES -> slot phase aligns per tile)
constexpr int A_BYTES = BM * BK * 2;                // 16384
constexpr int B_BYTES = BN * BK * 2;                // 32768
constexpr int STAGE_BYTES = A_BYTES + B_BYTES;      // 49152
constexpr int SMEM_DYN = STAGES * STAGE_BYTES + 1024;
constexpr int NT_N = N_DIM / BN;                    // 43
constexpr int NT_M = M_DIM / BM;                    // 64
constexpr int TOTAL_TILES = NT_N * NT_M;            // 2752

#define LDMX4(r0, r1, r2, r3, a) \
    asm volatile("ldmatrix.sync.aligned.m8n8.x4.shared.b16 {%0,%1,%2,%3}, [%4];" \
        : "=r"(r0), "=r"(r1), "=r"(r2), "=r"(r3) : "r"(a))
#define MMA16816(c, a, b) \
    asm volatile("mma.sync.aligned.m16n8k16.row.col.f32.bf16.bf16.f32 " \
        "{%0,%1,%2,%3}, {%4,%5,%6,%7}, {%8,%9}, {%0,%1,%2,%3};" \
        : "+f"((c)[0]), "+f"((c)[1]), "+f"((c)[2]), "+f"((c)[3]) \
        : "r"((a)[0]), "r"((a)[1]), "r"((a)[2]), "r"((a)[3]), "r"((b)[0]), "r"((b)[1]))
#define CP16(dst, src) \
    asm volatile("cp.async.cg.shared.global [%0], [%1], 16;" :: "r"(dst), "l"(src))
#define STG_CS_V2(p, vx, vy) \
    asm volatile("st.global.cs.v2.f32 [%0], {%1, %2};" :: "l"(p), "f"(vx), "f"(vy) : "memory")

// tile index -> (m0, n0) with GROUP_M=8 raster (8*43 = 344 tiles per panel)
__device__ __forceinline__ void tile_coords(int t, int& m0, int& n0) {
    int group = t / 344;
    int rem = t - group * 344;
    m0 = (group * 8 + (rem & 7)) * BM;
    n0 = (rem >> 3) * BN;
}

__global__ void __launch_bounds__(256, 1) gemm_kernel(float* __restrict__ out) {
    extern __shared__ char dyn_smem[];
    __shared__ int s_nxt;
    const int tid = threadIdx.x;
    const int wid = tid >> 5;
    const int lane = tid & 31;
    const int warp_m = wid >> 2;     // 0..1 (64 rows)
    const int warp_n = wid & 3;      // 0..3 (64 cols)

    uint32_t sbase = (smem_u32(dyn_smem) + 1023u) & ~1023u;

    // issue one 48KB stage: (tile, ks) -> smem slot (ks+? ) chosen by caller via slot arg
    auto issue_stage = [&](int tile, int ks, int slot) {
        if (tile < TOTAL_TILES) {
            int m0, n0;
            tile_coords(tile, m0, n0);
            const __nv_bfloat16* Ag = g_A + (size_t)m0 * K_DIM + ks * BK;
            const __nv_bfloat16* Bg = g_W + (size_t)n0 * K_DIM + ks * BK;
            uint32_t sa = sbase + slot * STAGE_BYTES;
            #pragma unroll
            for (int i = 0; i < 4; i++) {
                int c = tid + i * 256;
                int r = c >> 3, cc = c & 7;
                CP16(sa + SWZ(r * 128 + cc * 16),
                     (const void*)(Ag + (size_t)r * K_DIM + cc * 8));
            }
            #pragma unroll
            for (int i = 0; i < 8; i++) {
                int c = tid + i * 256;
                int r = c >> 3, cc = c & 7;
                CP16(sa + A_BYTES + SWZ(r * 128 + cc * 16),
                     (const void*)(Bg + (size_t)r * K_DIM + cc * 8));
            }
        }
        asm volatile("cp.async.commit_group;" ::: "memory");
    };

    const int lr = lane & 7;
    const int grp = lane >> 3;
    const int a_row_base = warp_m * 64 + (grp & 1) * 8 + lr;
    const int a_cb = (grp >> 1) * 16;
    const int b_row_base = warp_n * 64 + (grp >> 1) * 8 + lr;
    const int b_cb = (grp & 1) * 16;

    uint32_t af[2][4][4], bf[2][8][2];

    auto load_frags = [&](int slot, int kk, int buf) {
        uint32_t Abase = sbase + slot * STAGE_BYTES;
        uint32_t Bbase = Abase + A_BYTES;
        #pragma unroll
        for (int mi = 0; mi < 4; mi++) {
            uint32_t addr = Abase + SWZ((a_row_base + mi * 16) * 128 + kk * 32 + a_cb);
            LDMX4(af[buf][mi][0], af[buf][mi][1], af[buf][mi][2], af[buf][mi][3], addr);
        }
        #pragma unroll
        for (int p = 0; p < 4; p++) {
            uint32_t addr = Bbase + SWZ((b_row_base + p * 16) * 128 + kk * 32 + b_cb);
            LDMX4(bf[buf][2 * p][0], bf[buf][2 * p][1],
                  bf[buf][2 * p + 1][0], bf[buf][2 * p + 1][1], addr);
        }
    };

    float acc[4][8][4];

    auto mma_all = [&](int buf) {
        #pragma unroll
        for (int mi = 0; mi < 4; mi++)
            #pragma unroll
            for (int ni = 0; ni < 8; ni++)
                MMA16816(acc[mi][ni], af[buf][mi], bf[buf][ni]);
    };

    int cur = blockIdx.x;                 // static seed: tiles 0..NCTA-1

    // prologue: 3 stages of cur in flight (slots 0..2), frags (0,0) loaded
    issue_stage(cur, 0, 0);
    issue_stage(cur, 1, 1);
    issue_stage(cur, 2, 2);
    asm volatile("cp.async.wait_group 2;" ::: "memory");
    __syncthreads();
    load_frags(0, 0, 0);

    while (true) {
        #pragma unroll
        for (int mi = 0; mi < 4; mi++)
            #pragma unroll
            for (int ni = 0; ni < 8; ni++)
                #pragma unroll
                for (int q = 0; q < 4; q++) acc[mi][ni][q] = 0.0f;

        int nxt = TOTAL_TILES;            // filled at ks == KSTEPS-5
        for (int ks = 0; ks < KSTEPS; ks++) {
            const int slot = ks & (STAGES - 1);
            // prefetch 3 steps ahead into slot (ks-1)&3 (freed by last step's sync);
            // past the tile boundary this targets the next (stolen) tile's ks 0..2.
            if (ks < KSTEPS - 3) issue_stage(cur, ks + 3, (ks + 3) & (STAGES - 1));
            else                 issue_stage(nxt, ks + 3 - KSTEPS, (ks + 3) & (STAGES - 1));
            #pragma unroll
            for (int kk = 0; kk < 3; kk++) {
                load_frags(slot, kk + 1, (kk + 1) & 1);
                mma_all(kk & 1);
            }
            mma_all(1);      // kk=3 (operands register-resident)
            if (ks == KSTEPS - 5 && tid == 0) s_nxt = atomicAdd(&g_tile_ctr, 1);
            asm volatile("cp.async.wait_group 2;" ::: "memory");
            __syncthreads();
            if (ks == KSTEPS - 5) nxt = s_nxt;   // all threads read after the barrier
            load_frags((ks + 1) & (STAGES - 1), 0, 0);
        }

        // ---------- epilogue for cur (overlaps in-flight cp.async of nxt) ----------
        int m0, n0;
        tile_coords(cur, m0, n0);
        const int col0 = n0 + warp_n * 64 + (lane & 3) * 2;
        float sc[8][2];
        #pragma unroll
        for (int ni = 0; ni < 8; ni++) {
            sc[ni][0] = g_scale_col[col0 + ni * 8];
            sc[ni][1] = g_scale_col[col0 + ni * 8 + 1];
        }
        #pragma unroll
        for (int mi = 0; mi < 4; mi++) {
            int row0 = m0 + warp_m * 64 + mi * 16 + (lane >> 2);
            float xs0 = g_x_scale[row0];
            float xs1 = g_x_scale[row0 + 8];
            float* o0 = out + (size_t)row0 * N_DIM;
            float* o1 = o0 + (size_t)8 * N_DIM;
            #pragma unroll
            for (int ni = 0; ni < 8; ni++) {
                int c = col0 + ni * 8;
                STG_CS_V2(o0 + c, acc[mi][ni][0] * xs0 * sc[ni][0],
                                   acc[mi][ni][1] * xs0 * sc[ni][1]);
                STG_CS_V2(o1 + c, acc[mi][ni][2] * xs1 * sc[ni][0],
                                   acc[mi][ni][3] * xs1 * sc[ni][1]);
            }
        }

        if (nxt >= TOTAL_TILES) break;
        cur = nxt;
    }
}

// ---------- launch ----------
extern "C" void kernel_launch(void* const* d_in, const int* in_sizes, int n_in,
                              void* d_out, int out_size) {
    const float* x = (const float*)d_in[0];
    const float* w = (const float*)d_in[1];
    const float* sigma = (const float*)d_in[2];
    float* out = (float*)d_out;

    clear_mask_kernel<<<(K_DIM + 255) / 256, 256>>>();
    // fused weight-quant + outlier-mask: overlap their independent DRAM streams
    int mask_blocks = (int)(((size_t)M_DIM * K_DIM / 4) / 256);
    wq_mask_kernel<<<N_DIM + mask_blocks, 256>>>(w, x, sigma);
    rowquant_kernel<<<M_DIM, 256>>>(x);

    cudaFuncSetAttribute(gemm_kernel, cudaFuncAttributeMaxDynamicSharedMemorySize, SMEM_DYN);
    gemm_kernel<<<NCTA, 256, SMEM_DYN>>>(out);
}

// round 16
// speedup vs baseline: 1.8907x; 1.8907x over previous
#include <cuda_runtime.h>
#include <cuda_bf16.h>
#include <cstdint>

#define M_DIM 8192
#define K_DIM 4096
#define N_DIM 11008

// ---------- device scratch (no allocs allowed) ----------
__device__ __align__(256) __nv_bfloat16 g_A[(size_t)M_DIM * K_DIM];
__device__ __align__(256) __nv_bfloat16 g_W[(size_t)N_DIM * K_DIM];
__device__ float g_scale_col[N_DIM];
__device__ float g_x_scale[M_DIM];
__device__ int   g_mask[K_DIM];

// ---------- helpers ----------
__device__ __forceinline__ uint32_t smem_u32(const void* p) {
    uint32_t a;
    asm("{ .reg .u64 t; cvta.to.shared.u64 t, %1; cvt.u32.u64 %0, t; }" : "=r"(a) : "l"(p));
    return a;
}
#define SWZ(o) ((o) ^ (((o) >> 3) & 0x70))

__device__ __forceinline__ float block_max_256(float v) {
    __shared__ float red[8];
    #pragma unroll
    for (int o = 16; o > 0; o >>= 1) v = fmaxf(v, __shfl_xor_sync(0xffffffffu, v, o));
    if ((threadIdx.x & 31) == 0) red[threadIdx.x >> 5] = v;
    __syncthreads();
    if (threadIdx.x < 32) {
        float t = (threadIdx.x < 8) ? red[threadIdx.x] : 0.0f;
        #pragma unroll
        for (int o = 4; o > 0; o >>= 1) t = fmaxf(t, __shfl_xor_sync(0xffffffffu, t, o));
        if (threadIdx.x == 0) red[0] = t;
    }
    __syncthreads();
    return red[0];
}

// ---------- preprocessing ----------
__global__ void clear_mask_kernel() {
    int i = blockIdx.x * blockDim.x + threadIdx.x;
    if (i < K_DIM) g_mask[i] = 0;
}

// fused: blocks [0, N_DIM) do weight quant; blocks [N_DIM, ...) do the outlier mask.
__global__ void wq_mask_kernel(const float* __restrict__ w, const float* __restrict__ x,
                               const float* __restrict__ sigma) {
    if (blockIdx.x < N_DIM) {
        int n = blockIdx.x;
        const float4* row = reinterpret_cast<const float4*>(w + (size_t)n * K_DIM);
        float4 v[4];
        float mx = 0.0f;
        #pragma unroll
        for (int i = 0; i < 4; i++) {
            v[i] = row[threadIdx.x + i * 256];
            mx = fmaxf(mx, fmaxf(fmaxf(fabsf(v[i].x), fabsf(v[i].y)),
                                 fmaxf(fabsf(v[i].z), fabsf(v[i].w))));
        }
        mx = block_max_256(mx);
        float scale = mx * (1.0f / 64.0f);
        if (threadIdx.x == 0) g_scale_col[n] = scale;
        float inv = 1.0f / scale;
        ushort4* dst = reinterpret_cast<ushort4*>(g_W + (size_t)n * K_DIM);
        #pragma unroll
        for (int i = 0; i < 4; i++) {
            ushort4 u;
            u.x = __bfloat16_as_ushort(__float2bfloat16_rn(rintf(v[i].x * inv)));
            u.y = __bfloat16_as_ushort(__float2bfloat16_rn(rintf(v[i].y * inv)));
            u.z = __bfloat16_as_ushort(__float2bfloat16_rn(rintf(v[i].z * inv)));
            u.w = __bfloat16_as_ushort(__float2bfloat16_rn(rintf(v[i].w * inv)));
            dst[threadIdx.x + i * 256] = u;
        }
    } else {
        float sig = *sigma;
        size_t i = (size_t)(blockIdx.x - N_DIM) * blockDim.x + threadIdx.x;
        float4 v = reinterpret_cast<const float4*>(x)[i];
        int base = (int)((i * 4) & (K_DIM - 1));
        if (fabsf(v.x) > sig) g_mask[base + 0] = 1;
        if (fabsf(v.y) > sig) g_mask[base + 1] = 1;
        if (fabsf(v.z) > sig) g_mask[base + 2] = 1;
        if (fabsf(v.w) > sig) g_mask[base + 3] = 1;
    }
}

__global__ void rowquant_kernel(const float* __restrict__ x) {
    int m = blockIdx.x;
    const float4* row = reinterpret_cast<const float4*>(x + (size_t)m * K_DIM);
    const int4* mrow = reinterpret_cast<const int4*>(g_mask);
    float4 v[4];
    int4 mk[4];
    float mx = 0.0f;
    #pragma unroll
    for (int i = 0; i < 4; i++) {
        int f = threadIdx.x + i * 256;
        v[i] = row[f];
        mk[i] = mrow[f];
        if (!mk[i].x) mx = fmaxf(mx, fabsf(v[i].x));
        if (!mk[i].y) mx = fmaxf(mx, fabsf(v[i].y));
        if (!mk[i].z) mx = fmaxf(mx, fabsf(v[i].z));
        if (!mk[i].w) mx = fmaxf(mx, fabsf(v[i].w));
    }
    mx = block_max_256(mx);
    float xs = fmaxf(mx * (1.0f / 127.0f), 1e-8f);
    if (threadIdx.x == 0) g_x_scale[m] = xs;
    float inv = 1.0f / xs;
    ushort4* dst = reinterpret_cast<ushort4*>(g_A + (size_t)m * K_DIM);
    #pragma unroll
    for (int i = 0; i < 4; i++) {
        int f = threadIdx.x + i * 256;
        float q0 = v[i].x * inv; if (!mk[i].x) q0 = rintf(q0);
        float q1 = v[i].y * inv; if (!mk[i].y) q1 = rintf(q1);
        float q2 = v[i].z * inv; if (!mk[i].z) q2 = rintf(q2);
        float q3 = v[i].w * inv; if (!mk[i].w) q3 = rintf(q3);
        ushort4 u;
        u.x = __bfloat16_as_ushort(__float2bfloat16_rn(q0));
        u.y = __bfloat16_as_ushort(__float2bfloat16_rn(q1));
        u.z = __bfloat16_as_ushort(__float2bfloat16_rn(q2));
        u.w = __bfloat16_as_ushort(__float2bfloat16_rn(q3));
        dst[f] = u;
    }
}

// ---------- persistent GEMM: mma.sync bf16, 128x256x64 tile, 4 stages, piped frags ----------
constexpr int BM = 128, BN = 256, BK = 64;
constexpr int STAGES = 4;
constexpr int KSTEPS = K_DIM / BK;                  // 64
constexpr int A_BYTES = BM * BK * 2;                // 16384
constexpr int B_BYTES = BN * BK * 2;                // 32768
constexpr int STAGE_BYTES = A_BYTES + B_BYTES;      // 49152
constexpr int SMEM_DYN = STAGES * STAGE_BYTES + 1024;
constexpr int NT_N = N_DIM / BN;                    // 43
constexpr int NT_M = M_DIM / BM;                    // 64
constexpr int TOTAL_TILES = NT_N * NT_M;            // 2752
constexpr int NCTA = 148;

#define LDMX4(r0, r1, r2, r3, a) \
    asm volatile("ldmatrix.sync.aligned.m8n8.x4.shared.b16 {%0,%1,%2,%3}, [%4];" \
        : "=r"(r0), "=r"(r1), "=r"(r2), "=r"(r3) : "r"(a))
#define MMA16816(c, a, b) \
    asm volatile("mma.sync.aligned.m16n8k16.row.col.f32.bf16.bf16.f32 " \
        "{%0,%1,%2,%3}, {%4,%5,%6,%7}, {%8,%9}, {%0,%1,%2,%3};" \
        : "+f"((c)[0]), "+f"((c)[1]), "+f"((c)[2]), "+f"((c)[3]) \
        : "r"((a)[0]), "r"((a)[1]), "r"((a)[2]), "r"((a)[3]), "r"((b)[0]), "r"((b)[1]))
#define CP16(dst, src) \
    asm volatile("cp.async.cg.shared.global [%0], [%1], 16;" :: "r"(dst), "l"(src))
#define STG_CS_V2(p, vx, vy) \
    asm volatile("st.global.cs.v2.f32 [%0], {%1, %2};" :: "l"(p), "f"(vx), "f"(vy) : "memory")

// tile index -> (m0, n0) with GROUP_M=8 raster (8*43 = 344 tiles per panel)
__device__ __forceinline__ void tile_coords(int t, int& m0, int& n0) {
    int group = t / 344;
    int rem = t - group * 344;
    m0 = (group * 8 + (rem & 7)) * BM;
    n0 = (rem >> 3) * BN;
}

__global__ void __launch_bounds__(256, 1) gemm_kernel(float* __restrict__ out) {
    extern __shared__ char dyn_smem[];
    const int tid = threadIdx.x;
    const int wid = tid >> 5;
    const int lane = tid & 31;
    const int warp_m = wid >> 2;     // 0..1 (64 rows)
    const int warp_n = wid & 3;      // 0..3 (64 cols)
    const int bid = blockIdx.x;

    const int my_ntiles = (TOTAL_TILES - bid + NCTA - 1) / NCTA;

    uint32_t sbase = (smem_u32(dyn_smem) + 1023u) & ~1023u;

    // issue stage for per-CTA global step gs (= tile_i * KSTEPS + ks)
    auto issue_stage = [&](int gs) {
        int ti = gs >> 6;                 // local tile index
        if (ti < my_ntiles) {
            int m0, n0;
            tile_coords(bid + ti * NCTA, m0, n0);
            int ks = gs & 63;
            const __nv_bfloat16* Ag = g_A + (size_t)m0 * K_DIM + ks * BK;
            const __nv_bfloat16* Bg = g_W + (size_t)n0 * K_DIM + ks * BK;
            uint32_t sa = sbase + (gs & (STAGES - 1)) * STAGE_BYTES;
            #pragma unroll
            for (int i = 0; i < 4; i++) {
                int c = tid + i * 256;
                int r = c >> 3, cc = c & 7;
                CP16(sa + SWZ(r * 128 + cc * 16),
                     (const void*)(Ag + (size_t)r * K_DIM + cc * 8));
            }
            #pragma unroll
            for (int i = 0; i < 8; i++) {
                int c = tid + i * 256;
                int r = c >> 3, cc = c & 7;
                CP16(sa + A_BYTES + SWZ(r * 128 + cc * 16),
                     (const void*)(Bg + (size_t)r * K_DIM + cc * 8));
            }
        }
        asm volatile("cp.async.commit_group;" ::: "memory");
    };

    const int lr = lane & 7;
    const int grp = lane >> 3;
    const int a_row_base = warp_m * 64 + (grp & 1) * 8 + lr;
    const int a_cb = (grp >> 1) * 16;
    const int b_row_base = warp_n * 64 + (grp >> 1) * 8 + lr;
    const int b_cb = (grp & 1) * 16;

    uint32_t af[2][4][4], bf[2][8][2];

    auto load_frags = [&](int slot, int kk, int buf) {
        uint32_t Abase = sbase + slot * STAGE_BYTES;
        uint32_t Bbase = Abase + A_BYTES;
        #pragma unroll
        for (int mi = 0; mi < 4; mi++) {
            uint32_t addr = Abase + SWZ((a_row_base + mi * 16) * 128 + kk * 32 + a_cb);
            LDMX4(af[buf][mi][0], af[buf][mi][1], af[buf][mi][2], af[buf][mi][3], addr);
        }
        #pragma unroll
        for (int p = 0; p < 4; p++) {
            uint32_t addr = Bbase + SWZ((b_row_base + p * 16) * 128 + kk * 32 + b_cb);
            LDMX4(bf[buf][2 * p][0], bf[buf][2 * p][1],
                  bf[buf][2 * p + 1][0], bf[buf][2 * p + 1][1], addr);
        }
    };

    float acc[4][8][4];

    auto mma_all = [&](int buf) {
        #pragma unroll
        for (int mi = 0; mi < 4; mi++)
            #pragma unroll
            for (int ni = 0; ni < 8; ni++)
                MMA16816(acc[mi][ni], af[buf][mi], bf[buf][ni]);
    };

    // prologue: 3 stages of tile 0 in flight, frags for (0,0) loaded
    issue_stage(0);
    issue_stage(1);
    issue_stage(2);
    asm volatile("cp.async.wait_group 2;" ::: "memory");
    __syncthreads();
    load_frags(0, 0, 0);

    for (int ti = 0; ti < my_ntiles; ti++) {
        #pragma unroll
        for (int mi = 0; mi < 4; mi++)
            #pragma unroll
            for (int ni = 0; ni < 8; ni++)
                #pragma unroll
                for (int q = 0; q < 4; q++) acc[mi][ni][q] = 0.0f;

        const int gs0 = ti * KSTEPS;
        for (int ks = 0; ks < KSTEPS; ks++) {
            const int gs = gs0 + ks;
            const int slot = gs & (STAGES - 1);
            // EARLY issue: slot (gs+3)&3 == (gs-1)&3, freed by the sync that
            // ended step gs-1 (all its readers have passed).
            issue_stage(gs + 3);
            #pragma unroll
            for (int kk = 0; kk < 3; kk++) {
                load_frags(slot, kk + 1, (kk + 1) & 1);
                mma_all(kk & 1);
            }
            mma_all(1);      // kk=3 (operands register-resident)
            asm volatile("cp.async.wait_group 2;" ::: "memory");
            __syncthreads();
            load_frags((gs + 1) & (STAGES - 1), 0, 0);
        }

        // ---------- epilogue: streaming (evict-first) stores keep B panels in L2 ----------
        int m0, n0;
        tile_coords(bid + ti * NCTA, m0, n0);
        const int col0 = n0 + warp_n * 64 + (lane & 3) * 2;
        float sc[8][2];
        #pragma unroll
        for (int ni = 0; ni < 8; ni++) {
            sc[ni][0] = g_scale_col[col0 + ni * 8];
            sc[ni][1] = g_scale_col[col0 + ni * 8 + 1];
        }
        #pragma unroll
        for (int mi = 0; mi < 4; mi++) {
            int row0 = m0 + warp_m * 64 + mi * 16 + (lane >> 2);
            float xs0 = g_x_scale[row0];
            float xs1 = g_x_scale[row0 + 8];
            float* o0 = out + (size_t)row0 * N_DIM;
            float* o1 = o0 + (size_t)8 * N_DIM;
            #pragma unroll
            for (int ni = 0; ni < 8; ni++) {
                int c = col0 + ni * 8;
                STG_CS_V2(o0 + c, acc[mi][ni][0] * xs0 * sc[ni][0],
                                   acc[mi][ni][1] * xs0 * sc[ni][1]);
                STG_CS_V2(o1 + c, acc[mi][ni][2] * xs1 * sc[ni][0],
                                   acc[mi][ni][3] * xs1 * sc[ni][1]);
            }
        }
    }
}

// ---------- launch ----------
extern "C" void kernel_launch(void* const* d_in, const int* in_sizes, int n_in,
                              void* d_out, int out_size) {
    const float* x = (const float*)d_in[0];
    const float* w = (const float*)d_in[1];
    const float* sigma = (const float*)d_in[2];
    float* out = (float*)d_out;

    clear_mask_kernel<<<(K_DIM + 255) / 256, 256>>>();
    // fused weight-quant + outlier-mask: overlap their independent DRAM streams
    int mask_blocks = (int)(((size_t)M_DIM * K_DIM / 4) / 256);
    wq_mask_kernel<<<N_DIM + mask_blocks, 256>>>(w, x, sigma);
    rowquant_kernel<<<M_DIM, 256>>>(x);

    cudaFuncSetAttribute(gemm_kernel, cudaFuncAttributeMaxDynamicSharedMemorySize, SMEM_DYN);
    gemm_kernel<<<NCTA, 256, SMEM_DYN>>>(out);
}